// round 10
// baseline (speedup 1.0000x reference)
#include <cuda_runtime.h>
#include <mma.h>
#include <math.h>
#include <cstdint>

using namespace nvcuda;

// Problem constants
#define BB 32
#define CC 273
#define CP 288          // padded channel dim
#define TT 3000
#define OO 270
#define DD 2048
#define PH 1024

// Scratch
__device__ float g_tab[(size_t)BB * CC * 128];  // [bc][sx32|cx32|sy32|cy32]  ~4.5MB
__device__ float g_w[(size_t)BB * OO * CP];     // [b][o][c] padded

// ---------------------------------------------------------------------------
// cp.async helpers
// ---------------------------------------------------------------------------
__device__ __forceinline__ void cp_async16(float* smem, const float* gmem, bool pred) {
    unsigned int s = (unsigned int)__cvta_generic_to_shared(smem);
    int sz = pred ? 16 : 0;
    asm volatile("cp.async.cg.shared.global [%0], [%1], 16, %2;\n"
                 :: "r"(s), "l"(gmem), "r"(sz));
}
__device__ __forceinline__ void cp_commit() {
    asm volatile("cp.async.commit_group;\n" ::: "memory");
}
template <int N>
__device__ __forceinline__ void cp_wait() {
    asm volatile("cp.async.wait_group %0;\n" :: "n"(N) : "memory");
}

// ---------------------------------------------------------------------------
// Stage 0: per-(b,c) sincos tables. 64 threads: one sincos each.
// ---------------------------------------------------------------------------
__global__ __launch_bounds__(64) void tab_kernel(const float* __restrict__ layout) {
    int bc = blockIdx.x;
    int t  = threadIdx.x;
    const float two_pi = 6.28318530717958647692f;
    float p = (t < 32) ? layout[bc * 2 + 0] : layout[bc * 2 + 1];
    p = (p + 0.1f) / 1.2f;
    int i = t & 31;
    float a = p * (float)i;
    a -= floorf(a);
    float s, c;
    __sincosf(two_pi * a, &s, &c);
    float* row = g_tab + (size_t)bc * 128;
    if (t < 32) { row[i]      = s; row[32 + i] = c; }
    else        { row[64 + i] = s; row[96 + i] = c; }
}

// ---------------------------------------------------------------------------
// Stage 1: scores[b,o,c] = heads[o,:] . emb[b,c,:]  (tf32; emb generated from
// smem sincos tables — zero B-side gmem traffic). Block 96x96, BK=16,
// 6 warps (3x2), warp tile 32x48. 3-stage A prefetch, double-buffered gen B.
// ---------------------------------------------------------------------------
#define SKP 20

__global__ __launch_bounds__(192) void scores_kernel(const float* __restrict__ heads) {
    extern __shared__ float sm[];
    float* tab = sm;                     // 96*128 = 12288
    float* Asb = sm + 96 * 128;          // 3*96*20 = 5760
    float* Bsb = Asb + 3 * 96 * SKP;     // 2*96*20 = 3840

    int b  = blockIdx.z;
    int m0 = blockIdx.y * 96;            // o
    int n0 = blockIdx.x * 96;            // c
    int tid = threadIdx.x, warp = tid >> 5, lane = tid & 31;
    int wm = warp >> 1, wn = warp & 1;

    // Load sincos tables for this CTA's 96 channels (zero-fill past CC).
    {
        const float* tb = g_tab + ((size_t)b * CC) * 128;
        #pragma unroll
        for (int l = 0; l < 16; ++l) {
            int idx = tid + l * 192;           // 0..3071 float4 slots
            int row = idx >> 5, q = idx & 31;
            int c = n0 + row;
            float4 v = make_float4(0.f, 0.f, 0.f, 0.f);
            if (c < CC) v = *(const float4*)&tb[(size_t)c * 128 + q * 4];
            *(float4*)&tab[row * 128 + q * 4] = v;
        }
    }

    wmma::fragment<wmma::accumulator, 16, 16, 8, float> acc[2][3];
    #pragma unroll
    for (int i = 0; i < 2; ++i)
        #pragma unroll
        for (int j = 0; j < 3; ++j) wmma::fill_fragment(acc[i][j], 0.0f);

    const int NK = DD / 16;   // 128

    auto loadA = [&](int s, int k0) {
        float* As = Asb + s * 96 * SKP;
        #pragma unroll
        for (int l = 0; l < 2; ++l) {
            int idx = tid + l * 192;
            int row = idx >> 2, q = idx & 3;
            int o = m0 + row;
            cp_async16(&As[row * SKP + q * 4], &heads[(size_t)o * DD + k0 + q * 4], o < OO);
        }
        cp_commit();
    };

    loadA(0, 0);
    loadA(1, 16);

    for (int ks = 0; ks < NK; ++ks) {
        if (ks + 1 < NK) cp_wait<1>(); else cp_wait<0>();
        __syncthreads();                               // As[ks%3] visible; compute ks-1 done
        if (ks + 2 < NK) loadA((ks + 2) % 3, (ks + 2) * 16);

        // Generate B tile [96 x 16] for this K-step from tables.
        float* Bs = Bsb + (ks & 1) * 96 * SKP;
        int k0 = ks * 16;
        #pragma unroll
        for (int l = 0; l < 8; ++l) {
            int idx = tid + l * 192;                   // 0..1535
            int c  = idx >> 4, kk = idx & 15;
            int d  = k0 + kk;
            int dd = d & 1023;
            int i = dd >> 5, j = dd & 31;
            const float* tr = tab + c * 128;
            float sxv = tr[i], cxv = tr[32 + i], syv = tr[64 + j], cyv = tr[96 + j];
            float v = (d < PH) ? (sxv * cyv + cxv * syv)    // sin
                               : (cxv * cyv - sxv * syv);   // cos
            Bs[c * SKP + kk] = v;
        }
        __syncthreads();                               // publish Bs

        const float* As = Asb + (ks % 3) * 96 * SKP;
        #pragma unroll
        for (int kk = 0; kk < 16; kk += 8) {
            wmma::fragment<wmma::matrix_a, 16, 16, 8, wmma::precision::tf32, wmma::row_major> a[2];
            wmma::fragment<wmma::matrix_b, 16, 16, 8, wmma::precision::tf32, wmma::col_major> bf[3];
            #pragma unroll
            for (int i = 0; i < 2; ++i) {
                wmma::load_matrix_sync(a[i], &As[(wm * 32 + i * 16) * SKP + kk], SKP);
                #pragma unroll
                for (int e = 0; e < a[i].num_elements; ++e)
                    a[i].x[e] = wmma::__float_to_tf32(a[i].x[e]);
            }
            #pragma unroll
            for (int j = 0; j < 3; ++j) {
                wmma::load_matrix_sync(bf[j], &Bs[(wn * 48 + j * 16) * SKP + kk], SKP);
                #pragma unroll
                for (int e = 0; e < bf[j].num_elements; ++e)
                    bf[j].x[e] = wmma::__float_to_tf32(bf[j].x[e]);
            }
            #pragma unroll
            for (int i = 0; i < 2; ++i)
                #pragma unroll
                for (int j = 0; j < 3; ++j)
                    wmma::mma_sync(acc[i][j], a[i], bf[j], acc[i][j]);
        }
    }

    __syncthreads();
    // epilogue: per-warp patch space in As region
    float* patch = Asb + warp * 16 * SKP;
    float* wrow = g_w + (size_t)b * OO * CP;
    #pragma unroll
    for (int i = 0; i < 2; ++i) {
        #pragma unroll
        for (int j = 0; j < 3; ++j) {
            int r0 = m0 + wm * 32 + i * 16;
            int c0 = n0 + wn * 48 + j * 16;          // <= 272, +16 <= CP
            if (r0 + 16 <= OO) {
                wmma::store_matrix_sync(&wrow[(size_t)r0 * CP + c0], acc[i][j],
                                        CP, wmma::mem_row_major);
            } else {
                wmma::store_matrix_sync(patch, acc[i][j], SKP, wmma::mem_row_major);
                __syncwarp();
                for (int e = lane; e < 256; e += 32) {
                    int r = e >> 4, cc2 = e & 15;
                    if (r0 + r < OO)
                        wrow[(size_t)(r0 + r) * CP + c0 + cc2] = patch[r * SKP + cc2];
                }
                __syncwarp();
            }
        }
    }
}

// ---------------------------------------------------------------------------
// Stage 2: softmax over c (273 of 288) per (b,o) row; zero the pad.
// ---------------------------------------------------------------------------
__global__ __launch_bounds__(128) void softmax_kernel() {
    int row = blockIdx.x;
    float* s = g_w + (size_t)row * CP;
    int tid = threadIdx.x;
    __shared__ float sred[4];

    float m = -1e30f;
    for (int c = tid; c < CC; c += 128) m = fmaxf(m, s[c]);
    #pragma unroll
    for (int o = 16; o > 0; o >>= 1) m = fmaxf(m, __shfl_xor_sync(0xFFFFFFFFu, m, o));
    if ((tid & 31) == 0) sred[tid >> 5] = m;
    __syncthreads();
    m = fmaxf(fmaxf(sred[0], sred[1]), fmaxf(sred[2], sred[3]));
    __syncthreads();

    float sum = 0.f;
    for (int c = tid; c < CC; c += 128) {
        float e = __expf(s[c] - m);
        s[c] = e;
        sum += e;
    }
    #pragma unroll
    for (int o = 16; o > 0; o >>= 1) sum += __shfl_xor_sync(0xFFFFFFFFu, sum, o);
    if ((tid & 31) == 0) sred[tid >> 5] = sum;
    __syncthreads();
    sum = sred[0] + sred[1] + sred[2] + sred[3];

    float inv = 1.0f / sum;
    for (int c = tid; c < CP; c += 128) {
        if (c < CC) s[c] *= inv;
        else        s[c] = 0.f;
    }
}

// ---------------------------------------------------------------------------
// Stage 3: out[b,o,t] = sum_c w[b,o,c] * brain[b,c,t]
// Block 96x128, 192 threads (6 warps, 3x2), warp tile 32x64 (2x4 frags),
// 3-stage cp.async, ONE barrier per K-step. 2 CTAs/SM.
// ---------------------------------------------------------------------------
#define OBN  128
#define OBNP 132
#define OKP  20

__global__ __launch_bounds__(192) void out_kernel(const float* __restrict__ brain,
                                                  float* __restrict__ out) {
    // As[3][96][20]=5760 | Bs[3][16][132]=6336  -> 12096 floats = 48.4KB
    __shared__ float sm[3 * 96 * OKP + 3 * 16 * OBNP];
    float* Asb = sm;
    float* Bsb = sm + 3 * 96 * OKP;

    int b  = blockIdx.z;
    int m0 = blockIdx.y * 96;
    int n0 = blockIdx.x * OBN;
    int tid = threadIdx.x, warp = tid >> 5, lane = tid & 31;
    int wm = warp >> 1;                  // 0..2
    int wn = warp & 1;                   // 0..1

    const float* __restrict__ wB = g_w   + (size_t)b * OO * CP;
    const float* __restrict__ xB = brain + (size_t)b * CC * TT;

    wmma::fragment<wmma::accumulator, 16, 16, 8, float> acc[2][4];
    #pragma unroll
    for (int i = 0; i < 2; ++i)
        #pragma unroll
        for (int j = 0; j < 4; ++j) wmma::fill_fragment(acc[i][j], 0.0f);

    const int NK = CP / 16;   // 18

    auto load_tile = [&](int s, int k0) {
        float* As = Asb + s * 96 * OKP;
        float* Bs = Bsb + s * 16 * OBNP;
        #pragma unroll
        for (int l = 0; l < 2; ++l) {       // A: 96x16 = 384 float4 slots
            int idx = tid + l * 192;
            int row = idx >> 2, q = idx & 3;
            int o = m0 + row;
            cp_async16(&As[row * OKP + q * 4], &wB[(size_t)o * CP + k0 + q * 4], o < OO);
        }
        #pragma unroll
        for (int l = 0; l < 3; ++l) {       // B: 16x128 = 512 float4 slots
            int idx = tid + l * 192;
            if (idx < 512) {
                int row = idx >> 5, col = (idx & 31) << 2;
                int c = k0 + row, t = n0 + col;
                cp_async16(&Bs[row * OBNP + col], &xB[(size_t)c * TT + t],
                           (c < CC) && (t < TT));
            }
        }
        cp_commit();
    };

    load_tile(0, 0);
    load_tile(1, 16);

    for (int ks = 0; ks < NK; ++ks) {
        if (ks + 1 < NK) cp_wait<1>(); else cp_wait<0>();
        __syncthreads();                       // stage ks visible; compute ks-1 done
        if (ks + 2 < NK) load_tile((ks + 2) % 3, (ks + 2) * 16);

        const float* As = Asb + (ks % 3) * 96 * OKP;
        const float* Bs = Bsb + (ks % 3) * 16 * OBNP;
        #pragma unroll
        for (int kk = 0; kk < 16; kk += 8) {
            wmma::fragment<wmma::matrix_a, 16, 16, 8, wmma::precision::tf32, wmma::row_major> a[2];
            wmma::fragment<wmma::matrix_b, 16, 16, 8, wmma::precision::tf32, wmma::row_major> bf[4];
            #pragma unroll
            for (int i = 0; i < 2; ++i) {
                wmma::load_matrix_sync(a[i], &As[(wm * 32 + i * 16) * OKP + kk], OKP);
                #pragma unroll
                for (int e = 0; e < a[i].num_elements; ++e)
                    a[i].x[e] = wmma::__float_to_tf32(a[i].x[e]);
            }
            #pragma unroll
            for (int j = 0; j < 4; ++j) {
                wmma::load_matrix_sync(bf[j], &Bs[kk * OBNP + wn * 64 + j * 16], OBNP);
                #pragma unroll
                for (int e = 0; e < bf[j].num_elements; ++e)
                    bf[j].x[e] = wmma::__float_to_tf32(bf[j].x[e]);
            }
            #pragma unroll
            for (int i = 0; i < 2; ++i)
                #pragma unroll
                for (int j = 0; j < 4; ++j)
                    wmma::mma_sync(acc[i][j], a[i], bf[j], acc[i][j]);
        }
    }

    __syncthreads();
    float* patch = Asb + warp * 16 * OKP;
    #pragma unroll
    for (int i = 0; i < 2; ++i) {
        #pragma unroll
        for (int j = 0; j < 4; ++j) {
            int r0 = m0 + wm * 32 + i * 16;
            int t0 = n0 + wn * 64 + j * 16;
            if (r0 + 16 <= OO && t0 + 16 <= TT) {
                wmma::store_matrix_sync(&out[((size_t)b * OO + r0) * TT + t0],
                                        acc[i][j], TT, wmma::mem_row_major);
            } else {
                wmma::store_matrix_sync(patch, acc[i][j], OKP, wmma::mem_row_major);
                __syncwarp();
                for (int e = lane; e < 256; e += 32) {
                    int r = e >> 4, cc2 = e & 15;
                    int o = r0 + r, t = t0 + cc2;
                    if (o < OO && t < TT)
                        out[((size_t)b * OO + o) * TT + t] = patch[r * OKP + cc2];
                }
                __syncwarp();
            }
        }
    }
}

// ---------------------------------------------------------------------------
// Launch
// ---------------------------------------------------------------------------
#define SCORES_SMEM ((96 * 128 + 3 * 96 * SKP + 2 * 96 * SKP) * 4)   // 87552 B

extern "C" void kernel_launch(void* const* d_in, const int* in_sizes, int n_in,
                              void* d_out, int out_size) {
    const float* brain  = (const float*)d_in[0];   // [32, 273, 3000]
    const float* layout = (const float*)d_in[1];   // [32, 273, 2]
    const float* heads  = (const float*)d_in[2];   // [270, 2048]
    float* out = (float*)d_out;                    // [32, 270, 3000]

    cudaFuncSetAttribute(scores_kernel,
                         cudaFuncAttributeMaxDynamicSharedMemorySize, SCORES_SMEM);

    tab_kernel<<<BB * CC, 64>>>(layout);

    dim3 gs((CP + 95) / 96, (OO + 95) / 96, BB);          // (3, 3, 32)
    scores_kernel<<<gs, 192, SCORES_SMEM>>>(heads);

    softmax_kernel<<<BB * OO, 128>>>();

    dim3 go((TT + OBN - 1) / OBN, (OO + 95) / 96, BB);    // (24, 3, 32)
    out_kernel<<<go, 192>>>(brain, out);
}